// round 3
// baseline (speedup 1.0000x reference)
#include <cuda_runtime.h>
#include <cstddef>

// Problem constants (match reference)
#define BATCH 256
#define SEQ   780
#define DIM   1024
#define MAXT  195
// DIM/4 = 256 float4 lanes per row
#define THREADS 256

// One CTA per (batch, pooled-token). Valid tokens: gather 4 rows, average.
// Invalid tokens: write a zero row. Attention written by lane 0.
__global__ void __launch_bounds__(THREADS, 8)
avg_pool_merge_kernel(const float* __restrict__ hs,
                      const int*   __restrict__ grid_thw,
                      float*       __restrict__ out,
                      float*       __restrict__ out_att)
{
    const int j = blockIdx.x;   // pooled token index [0, MAXT)
    const int b = blockIdx.y;   // batch index
    const int t = threadIdx.x;  // float4 lane [0, 256)

    // Per-sample pooled geometry (tiny, L2/L1 resident after first wave)
    const int H2 = grid_thw[b * 3 + 1] >> 1;
    const int W2 = grid_thw[b * 3 + 2] >> 1;
    const int Hp = H2 >> 1;
    const int Wp = W2 >> 1;
    const int n_out = Hp * Wp;

    float4* o = reinterpret_cast<float4*>(
        out + ((size_t)b * MAXT + j) * DIM) + t;

    if (j >= n_out) {
        *o = make_float4(0.f, 0.f, 0.f, 0.f);
        if (t == 0 && out_att) out_att[(size_t)b * MAXT + j] = 0.f;
        return;
    }

    const int r = j / Wp;
    const int c = j - r * Wp;
    const int base = (2 * r) * W2 + 2 * c;  // top-left token of 2x2 window

    const float* srow = hs + (size_t)b * SEQ * DIM;
    const float4* p0 = reinterpret_cast<const float4*>(srow + (size_t)(base         ) * DIM) + t;
    const float4* p1 = reinterpret_cast<const float4*>(srow + (size_t)(base + 1     ) * DIM) + t;
    const float4* p2 = reinterpret_cast<const float4*>(srow + (size_t)(base + W2    ) * DIM) + t;
    const float4* p3 = reinterpret_cast<const float4*>(srow + (size_t)(base + W2 + 1) * DIM) + t;

    const float4 v0 = *p0;
    const float4 v1 = *p1;
    const float4 v2 = *p2;
    const float4 v3 = *p3;

    float4 s;
    s.x = (v0.x + v1.x + v2.x + v3.x) * 0.25f;
    s.y = (v0.y + v1.y + v2.y + v3.y) * 0.25f;
    s.z = (v0.z + v1.z + v2.z + v3.z) * 0.25f;
    s.w = (v0.w + v1.w + v2.w + v3.w) * 0.25f;
    *o = s;

    if (t == 0 && out_att) out_att[(size_t)b * MAXT + j] = 1.f;
}

extern "C" void kernel_launch(void* const* d_in, const int* in_sizes, int n_in,
                              void* d_out, int out_size)
{
    const float* hs       = (const float*)d_in[0];  // [B, S, D] float32
    // d_in[1] = attention_mask (int32, all ones) — value unused by reference math
    const int*   grid_thw = (const int*)d_in[2];    // [B, 3] int32

    float* out = (float*)d_out;
    const long long main_elems = (long long)BATCH * MAXT * DIM;
    const long long att_elems  = (long long)BATCH * MAXT;
    // Tuple output concatenated (outputs, outputs_attention) if out_size covers both.
    float* out_att = ((long long)out_size >= main_elems + att_elems)
                         ? out + main_elems : nullptr;

    dim3 grid(MAXT, BATCH);
    avg_pool_merge_kernel<<<grid, THREADS>>>(hs, grid_thw, out, out_att);
}